// round 14
// baseline (speedup 1.0000x reference)
#include <cuda_runtime.h>
#include <cuda_fp16.h>
#include <math.h>

#define SEQL   2048
#define BATCH  64
#define INDIM  512
#define HID    512
#define NCTA   128
#define NTHR   512

// smem byte offsets
#define ACT_OFF   0               // 66560: x tile (canonical W during setup)
#define WIHF_OFF  66560           // 32768: Wih b-fragments [nt][kh][chunk][lane] uint4
#define WHHF_OFF  99328           // 32768: Whh b-fragments
#define P_OFF     132096          // float [2][64][18] = 9216
#define BIAS_OFF  141312          // 16 floats
#define F0_OFF    141376
#define SMEM_TOTAL 141392

__device__ unsigned g_flags[NCTA];                                // monotonic across runs
__device__ __align__(16) __half g_xh[(size_t)SEQL * BATCH * 512]; // fp16 x
__device__ __align__(16) __half g_hf[2][BATCH * 512];             // ping-pong fp16 h

__device__ __forceinline__ float sigm(float x){
    return __fdividef(1.0f, 1.0f + __expf(-x));
}
__device__ __forceinline__ float ftanh(float x){
    float e = __expf(-2.0f * x);
    return __fdividef(1.0f - e, 1.0f + e);
}

// ---- cp.async ----
__device__ __forceinline__ void cp16(unsigned s, const void* g){
    asm volatile("cp.async.cg.shared.global [%0], [%1], 16;" :: "r"(s), "l"(g) : "memory");
}
__device__ __forceinline__ void cp_commit(){ asm volatile("cp.async.commit_group;" ::: "memory"); }
template<int N> __device__ __forceinline__ void cp_wait(){
    asm volatile("cp.async.wait_group %0;" :: "n"(N) : "memory");
}

// ---- flags ----
__device__ __forceinline__ void st_rel(unsigned* p, unsigned v){
    asm volatile("st.release.gpu.u32 [%0], %1;" :: "l"(p), "r"(v) : "memory");
}
__device__ __forceinline__ unsigned ld_acq(unsigned* p){
    unsigned v; asm volatile("ld.acquire.gpu.u32 %0, [%1];" : "=r"(v) : "l"(p) : "memory");
    return v;
}

// ---- L1-bypassing global load (h exchange; L1 is stale across steps) ----
#define LDGCG(v, p) asm volatile("ld.global.cg.b32 %0, [%1];" : "=r"(v) : "l"(p))

// ---- tensor-core primitives ----
__device__ __forceinline__ void ldsm4(unsigned a, unsigned &r0, unsigned &r1,
                                      unsigned &r2, unsigned &r3){
    asm volatile("ldmatrix.sync.aligned.m8n8.x4.shared.b16 {%0,%1,%2,%3}, [%4];"
                 : "=r"(r0), "=r"(r1), "=r"(r2), "=r"(r3) : "r"(a));
}
__device__ __forceinline__ void ldsm2(unsigned a, unsigned &r0, unsigned &r1){
    asm volatile("ldmatrix.sync.aligned.m8n8.x2.shared.b16 {%0,%1}, [%2];"
                 : "=r"(r0), "=r"(r1) : "r"(a));
}
__device__ __forceinline__ void lds128(unsigned a, unsigned &r0, unsigned &r1,
                                       unsigned &r2, unsigned &r3){
    asm volatile("ld.shared.v4.u32 {%0,%1,%2,%3}, [%4];"
                 : "=r"(r0), "=r"(r1), "=r"(r2), "=r"(r3) : "r"(a));
}
__device__ __forceinline__ void sts128(unsigned a, unsigned r0, unsigned r1,
                                       unsigned r2, unsigned r3){
    asm volatile("st.shared.v4.b32 [%0], {%1,%2,%3,%4};"
                 :: "r"(a), "r"(r0), "r"(r1), "r"(r2), "r"(r3) : "memory");
}
__device__ __forceinline__ void mmaf16(float &c0, float &c1, float &c2, float &c3,
                                       unsigned a0, unsigned a1, unsigned a2, unsigned a3,
                                       unsigned b0, unsigned b1){
    asm volatile("mma.sync.aligned.m16n8k16.row.col.f32.f16.f16.f32 "
                 "{%0,%1,%2,%3}, {%4,%5,%6,%7}, {%8,%9}, {%0,%1,%2,%3};"
                 : "+f"(c0), "+f"(c1), "+f"(c2), "+f"(c3)
                 : "r"(a0), "r"(a1), "r"(a2), "r"(a3), "r"(b0), "r"(b1));
}

// ============ kernel 1: x fp32 -> fp16 ============
__global__ void __launch_bounds__(256, 4)
xconv(const float* __restrict__ in)
{
    int t = blockIdx.x;
    const float4* src = (const float4*)(in + (size_t)t * BATCH * INDIM);
    __half2* dst = (__half2*)(g_xh + (size_t)t * BATCH * 512);
    for (int i = threadIdx.x; i < BATCH * INDIM / 4; i += 256) {
        float4 v = src[i];
        dst[i * 2]     = __floats2half2_rn(v.x, v.y);
        dst[i * 2 + 1] = __floats2half2_rn(v.z, v.w);
    }
}

// ============ kernel 2: fused persistent LSTM ============
__global__ void __launch_bounds__(NTHR, 1)
lstm_persistent(const float* __restrict__ Wih,
                const float* __restrict__ Whh,
                const float* __restrict__ bih,
                const float* __restrict__ bhh,
                float* __restrict__ out)
{
    extern __shared__ char sm[];
    const unsigned sb = (unsigned)__cvta_generic_to_shared(sm);
    float* part = (float*)(sm + P_OFF);
    float* bias = (float*)(sm + BIAS_OFF);
    unsigned* sF0 = (unsigned*)(sm + F0_OFF);

    const int tid = threadIdx.x;
    const int cta = blockIdx.x;
    const int hc0 = cta * 4;

    if (tid == 0) *sF0 = g_flags[cta];

    // ---- canonical weights (fp16 hi/lo) into ACT region temporarily ----
    for (int i = tid; i < 16 * 512; i += NTHR) {
        int r = i >> 9, k = i & 511;
        int grow = (r >> 2) * 512 + hc0 + (r & 3);
        float w = Wih[(size_t)grow * INDIM + k];
        __half h = __float2half(w);
        *(__half*)(sm + ACT_OFF + 0*16640 + r*1040 + k*2) = h;
        *(__half*)(sm + ACT_OFF + 1*16640 + r*1040 + k*2) = __float2half(w - __half2float(h));
        w = Whh[(size_t)grow * HID + k];
        h = __float2half(w);
        *(__half*)(sm + ACT_OFF + 2*16640 + r*1040 + k*2) = h;
        *(__half*)(sm + ACT_OFF + 3*16640 + r*1040 + k*2) = __float2half(w - __half2float(h));
    }
    if (tid < 16) {
        int grow = (tid >> 2) * 512 + hc0 + (tid & 3);
        bias[tid] = bih[grow] + bhh[grow];
    }
    __syncthreads();

    // ---- warp identity: mt(4 batch-tiles) x nt(2 row-tiles) x kh(2 K-halves) ----
    const int wid = tid >> 5, lane = tid & 31;
    const int mt = wid & 3, nt = (wid >> 2) & 1, kh = wid >> 3;

    // ---- pre-swizzle weight b-fragments into smem (warps with mt==0) ----
    if (mt == 0) {
        unsigned cbase = sb + ACT_OFF + (unsigned)((nt*8 + (lane & 7))*1040
                                                   + ((lane >> 3) & 1)*16 + kh*512);
        unsigned fdsti = sb + WIHF_OFF + (unsigned)((nt*2 + kh)*8192 + lane*16);
        unsigned fdsth = sb + WHHF_OFF + (unsigned)((nt*2 + kh)*8192 + lane*16);
#pragma unroll
        for (int c = 0; c < 16; ++c) {
            unsigned h0,h1,l0,l1;
            ldsm2(cbase + c*32,           h0, h1);   // ih hi
            ldsm2(cbase + 16640 + c*32,   l0, l1);   // ih lo
            sts128(fdsti + c*512, h0, h1, l0, l1);
            ldsm2(cbase + 2*16640 + c*32, h0, h1);   // hh hi
            ldsm2(cbase + 3*16640 + c*32, l0, l1);   // hh lo
            sts128(fdsth + c*512, h0, h1, l0, l1);
        }
    }
    __syncthreads();                                 // frags ready; ACT reusable

    // ---- prefetch x_0 ----
    for (int i = tid; i < 4096; i += NTHR) {
        int row = i >> 6, u = i & 63;
        cp16(sb + (unsigned)(ACT_OFF + row*1040 + u*16), g_xh + row*512 + u*8);
    }
    cp_commit();

    const unsigned F0 = *sF0;

    const unsigned aBase = sb + (unsigned)(ACT_OFF + (mt*16 + (lane & 15))*1040
                                           + (lane >> 4)*16 + kh*512);
    const unsigned fIh = sb + WIHF_OFF + (unsigned)((nt*2 + kh)*8192 + lane*16);
    const unsigned fHh = sb + WHHF_OFF + (unsigned)((nt*2 + kh)*8192 + lane*16);

    // h fragment gather base (bytes into a 64x512 fp16 row-major buffer)
    const int hoff = (mt*16 + (lane >> 2))*1024 + (lane & 3)*4 + kh*512;

    const int prow = mt*16 + (lane >> 2);
    const int pcol = nt*8 + (lane & 3)*2;
    float* pp = part + (kh*64 + prow)*18 + pcol;

    const int ub = tid >> 2, uhcl = tid & 3;
    unsigned* fp = &g_flags[(wid << 3) + (lane & 7)];

    float cst = 0.0f;

    for (int t = 0; t < SEQL; ++t) {
        cp_wait<0>(); __syncthreads();               // x_t staged

        const unsigned tgt = F0 + (unsigned)t;
        unsigned fpre = 0;
        if (t > 0) fpre = ld_acq(fp);                // early flag probe (hidden under x-GEMM)

        float c0 = 0.f, c1 = 0.f, c2 = 0.f, c3 = 0.f;

        // ---- x-GEMM: 16 chunks (a via ldmatrix, b via one LDS.128 hi+lo) ----
#pragma unroll 4
        for (int c = 0; c < 16; ++c) {
            unsigned a0,a1,a2,a3, b0,b1,b2,b3;
            ldsm4(aBase + c*32, a0,a1,a2,a3);
            lds128(fIh + c*512, b0,b1,b2,b3);
            mmaf16(c0,c1,c2,c3, a0,a1,a2,a3, b0,b1);
            mmaf16(c0,c1,c2,c3, a0,a1,a2,a3, b2,b3);
        }
        __syncthreads();                             // ACT dead

        // ---- prefetch x_{t+1} (flight spans h + update phases) ----
        if (t + 1 < SEQL) {
            const __half* gx = g_xh + (size_t)(t + 1) * BATCH * 512;
            for (int i = tid; i < 4096; i += NTHR) {
                int row = i >> 6, u = i & 63;
                cp16(sb + (unsigned)(ACT_OFF + row*1040 + u*16), gx + row*512 + u*8);
            }
            cp_commit();
        }

        if (t > 0) {
            // ---- finish poll (usually already satisfied) ----
            if (!__all_sync(0xffffffffu, (int)(fpre - tgt) >= 0)) {
                for (;;) {
                    unsigned f = ld_acq(fp);
                    if (__all_sync(0xffffffffu, (int)(f - tgt) >= 0)) break;
                }
            }
            __syncthreads();                         // block-wide AND of flag slices

            // ---- h-MMA: direct LDG.cg a-fragments, pipelined 4 deep ----
            const char* hs = (const char*)g_hf[(t - 1) & 1] + hoff;
            unsigned h0[4], h1[4], h2[4], h3[4];
#pragma unroll
            for (int p = 0; p < 4; ++p) {
                const char* p0 = hs + p*32;
                LDGCG(h0[p], p0);        LDGCG(h1[p], p0 + 8192);
                LDGCG(h2[p], p0 + 16);   LDGCG(h3[p], p0 + 8192 + 16);
            }
#pragma unroll
            for (int c = 0; c < 16; ++c) {
                int s = c & 3;
                unsigned b0,b1,b2,b3;
                lds128(fHh + c*512, b0,b1,b2,b3);
                mmaf16(c0,c1,c2,c3, h0[s],h1[s],h2[s],h3[s], b0,b1);
                mmaf16(c0,c1,c2,c3, h0[s],h1[s],h2[s],h3[s], b2,b3);
                if (c < 12) {
                    const char* p0 = hs + (c + 4)*32;
                    LDGCG(h0[s], p0);        LDGCG(h1[s], p0 + 8192);
                    LDGCG(h2[s], p0 + 16);   LDGCG(h3[s], p0 + 8192 + 16);
                }
            }
        }

        // ---- K-half partials ----
        pp[0] = c0; pp[1] = c1; pp[144] = c2; pp[145] = c3;
        __syncthreads();

        if (tid < 256) {
            float sv[4];
#pragma unroll
            for (int g = 0; g < 4; ++g) {
                int r = g*4 + uhcl;
                sv[g] = bias[r] + part[ub*18 + r] + part[(64 + ub)*18 + r];
            }
            float ig = sigm(sv[0]);
            float fg = sigm(sv[1]);
            float gv = ftanh(sv[2]);
            float og = sigm(sv[3]);
            float cn = fmaf(fg, cst, ig * gv);
            cst = cn;
            float hn = og * ftanh(cn);

            // publish h first, release, THEN the out stores (off critical path)
            g_hf[t & 1][ub*512 + hc0 + uhcl] = __float2half(hn);
            asm volatile("bar.sync 1, 256;" ::: "memory");
            if (tid == 0) st_rel(&g_flags[cta], F0 + (unsigned)(t + 1));

            out[(size_t)t * BATCH * HID + (size_t)ub * HID + hc0 + uhcl] = hn;
            if (t == SEQL - 1)
                out[(size_t)SEQL * BATCH * HID + (size_t)ub * HID + hc0 + uhcl] = hn;
        }
    }

    // c_n
    if (tid < 256)
        out[(size_t)SEQL * BATCH * HID + (size_t)BATCH * HID
            + (size_t)ub * HID + hc0 + uhcl] = cst;
}

extern "C" void kernel_launch(void* const* d_in, const int* in_sizes, int n_in,
                              void* d_out, int out_size)
{
    const float* input = (const float*)d_in[0];
    const float* Wih   = (const float*)d_in[1];
    const float* Whh   = (const float*)d_in[2];
    const float* bih   = (const float*)d_in[3];
    const float* bhh   = (const float*)d_in[4];
    float* out = (float*)d_out;

    static int configured = 0;
    if (!configured) {
        cudaFuncSetAttribute(lstm_persistent,
                             cudaFuncAttributeMaxDynamicSharedMemorySize, SMEM_TOTAL);
        configured = 1;
    }

    xconv<<<SEQL, 256>>>(input);
    lstm_persistent<<<NCTA, NTHR, SMEM_TOTAL>>>(Wih, Whh, bih, bhh, out);
}

// round 15
// speedup vs baseline: 2.9214x; 2.9214x over previous
#include <cuda_runtime.h>
#include <cuda_fp16.h>
#include <math.h>

#define SEQL   2048
#define BATCH  64
#define INDIM  512
#define HID    512
#define NCTA   128
#define NTHR   512

// smem byte offsets
#define XA_OFF   0            // 32 rows x 1040 B (x tile, group A)  [canonical W at setup]
#define XB_OFF   33280        // x tile, group B
#define HA_OFF   66560        // h tile, group A
#define HB_OFF   99840        // h tile, group B
#define FIH_OFF  133120       // Wih frags: [nt*4+kq][chunk][lane] uint4 = 32768
#define FHH_OFF  165888       // Whh frags
#define PA_OFF   198656       // float [4][32][18] = 9216
#define PB_OFF   207872
#define BIAS_OFF 217088       // 16 floats
#define F0_OFF   217152       // 2 unsigned
#define SMEM_TOTAL 217168

__device__ unsigned g_flagsA[NCTA];                               // monotonic across runs
__device__ unsigned g_flagsB[NCTA];
__device__ __align__(16) __half g_xh[(size_t)SEQL * BATCH * 512]; // fp16 x
__device__ __align__(16) __half g_hA[2][32 * 512];                // ping-pong fp16 h, group A
__device__ __align__(16) __half g_hB[2][32 * 512];                // group B

__device__ __forceinline__ float sigm(float x){
    return __fdividef(1.0f, 1.0f + __expf(-x));
}
__device__ __forceinline__ float ftanh(float x){
    float e = __expf(-2.0f * x);
    return __fdividef(1.0f - e, 1.0f + e);
}

// ---- cp.async ----
__device__ __forceinline__ void cp16(unsigned s, const void* g){
    asm volatile("cp.async.cg.shared.global [%0], [%1], 16;" :: "r"(s), "l"(g) : "memory");
}
__device__ __forceinline__ void cp_commit(){ asm volatile("cp.async.commit_group;" ::: "memory"); }
__device__ __forceinline__ void cp_wait0(){ asm volatile("cp.async.wait_group 0;" ::: "memory"); }

// ---- flags ----
__device__ __forceinline__ void st_rel(unsigned* p, unsigned v){
    asm volatile("st.release.gpu.u32 [%0], %1;" :: "l"(p), "r"(v) : "memory");
}
__device__ __forceinline__ unsigned ld_acq(unsigned* p){
    unsigned v; asm volatile("ld.acquire.gpu.u32 %0, [%1];" : "=r"(v) : "l"(p) : "memory");
    return v;
}

// ---- tensor-core primitives ----
__device__ __forceinline__ void ldsm4(unsigned a, unsigned &r0, unsigned &r1,
                                      unsigned &r2, unsigned &r3){
    asm volatile("ldmatrix.sync.aligned.m8n8.x4.shared.b16 {%0,%1,%2,%3}, [%4];"
                 : "=r"(r0), "=r"(r1), "=r"(r2), "=r"(r3) : "r"(a));
}
__device__ __forceinline__ void ldsm2(unsigned a, unsigned &r0, unsigned &r1){
    asm volatile("ldmatrix.sync.aligned.m8n8.x2.shared.b16 {%0,%1}, [%2];"
                 : "=r"(r0), "=r"(r1) : "r"(a));
}
__device__ __forceinline__ void lds128(unsigned a, unsigned &r0, unsigned &r1,
                                       unsigned &r2, unsigned &r3){
    asm volatile("ld.shared.v4.u32 {%0,%1,%2,%3}, [%4];"
                 : "=r"(r0), "=r"(r1), "=r"(r2), "=r"(r3) : "r"(a));
}
__device__ __forceinline__ void sts128(unsigned a, unsigned r0, unsigned r1,
                                       unsigned r2, unsigned r3){
    asm volatile("st.shared.v4.b32 [%0], {%1,%2,%3,%4};"
                 :: "r"(a), "r"(r0), "r"(r1), "r"(r2), "r"(r3) : "memory");
}
__device__ __forceinline__ void mmaf16(float &c0, float &c1, float &c2, float &c3,
                                       unsigned a0, unsigned a1, unsigned a2, unsigned a3,
                                       unsigned b0, unsigned b1){
    asm volatile("mma.sync.aligned.m16n8k16.row.col.f32.f16.f16.f32 "
                 "{%0,%1,%2,%3}, {%4,%5,%6,%7}, {%8,%9}, {%0,%1,%2,%3};"
                 : "+f"(c0), "+f"(c1), "+f"(c2), "+f"(c3)
                 : "r"(a0), "r"(a1), "r"(a2), "r"(a3), "r"(b0), "r"(b1));
}

// ============ kernel 1: x fp32 -> fp16 ============
__global__ void __launch_bounds__(256, 4)
xconv(const float* __restrict__ in)
{
    int t = blockIdx.x;
    const float4* src = (const float4*)(in + (size_t)t * BATCH * INDIM);
    __half2* dst = (__half2*)(g_xh + (size_t)t * BATCH * 512);
    for (int i = threadIdx.x; i < BATCH * INDIM / 4; i += 256) {
        float4 v = src[i];
        dst[i * 2]     = __floats2half2_rn(v.x, v.y);
        dst[i * 2 + 1] = __floats2half2_rn(v.z, v.w);
    }
}

// ============ kernel 2: fused persistent LSTM, 2-group batch pipeline ============
__global__ void __launch_bounds__(NTHR, 1)
lstm_persistent(const float* __restrict__ Wih,
                const float* __restrict__ Whh,
                const float* __restrict__ bih,
                const float* __restrict__ bhh,
                float* __restrict__ out)
{
    extern __shared__ char sm[];
    const unsigned sb = (unsigned)__cvta_generic_to_shared(sm);
    float* partA = (float*)(sm + PA_OFF);
    float* partB = (float*)(sm + PB_OFF);
    float* bias  = (float*)(sm + BIAS_OFF);
    unsigned* sF0 = (unsigned*)(sm + F0_OFF);

    const int tid = threadIdx.x;
    const int cta = blockIdx.x;
    const int hc0 = cta * 4;

    if (tid == 0) { sF0[0] = g_flagsA[cta]; sF0[1] = g_flagsB[cta]; }

    // ---- canonical weights (fp16 hi/lo) into XA/XB region temporarily ----
    // layout: Wih_hi @ XA+0, Wih_lo @ +16640, Whh_hi @ +33280, Whh_lo @ +49920
    for (int i = tid; i < 16 * 512; i += NTHR) {
        int r = i >> 9, k = i & 511;
        int grow = (r >> 2) * 512 + hc0 + (r & 3);
        float w = Wih[(size_t)grow * INDIM + k];
        __half h = __float2half(w);
        *(__half*)(sm + XA_OFF + 0*16640 + r*1040 + k*2) = h;
        *(__half*)(sm + XA_OFF + 1*16640 + r*1040 + k*2) = __float2half(w - __half2float(h));
        w = Whh[(size_t)grow * HID + k];
        h = __float2half(w);
        *(__half*)(sm + XA_OFF + 2*16640 + r*1040 + k*2) = h;
        *(__half*)(sm + XA_OFF + 3*16640 + r*1040 + k*2) = __float2half(w - __half2float(h));
    }
    if (tid < 16) {
        int grow = (tid >> 2) * 512 + hc0 + (tid & 3);
        bias[tid] = bih[grow] + bhh[grow];
    }
    __syncthreads();

    const int wid = tid >> 5, lane = tid & 31;
    // warp identity: mt(2 x 16-row batch tiles) x nt(2 x 8-row gate tiles) x kq(4 K-quarters)
    const int mt = wid & 1, nt = (wid >> 1) & 1, kq = wid >> 2;

    // ---- pre-swizzle weight b-fragments (warps 0-7: (ntS, kqS)) ----
    if (wid < 8) {
        int ntS = wid >> 2, kqS = wid & 3;
        unsigned cb = sb + XA_OFF + (unsigned)((ntS*8 + (lane & 7))*1040
                                               + ((lane >> 3) & 1)*16 + kqS*256);
        unsigned fi = sb + FIH_OFF + (unsigned)(((ntS*4 + kqS)*8)*512 + lane*16);
        unsigned fh = sb + FHH_OFF + (unsigned)(((ntS*4 + kqS)*8)*512 + lane*16);
#pragma unroll
        for (int c = 0; c < 8; ++c) {
            unsigned h0,h1,l0,l1;
            ldsm2(cb + c*32,           h0, h1);        // ih hi
            ldsm2(cb + 16640 + c*32,   l0, l1);        // ih lo
            sts128(fi + c*512, h0, h1, l0, l1);
            ldsm2(cb + 2*16640 + c*32, h0, h1);        // hh hi
            ldsm2(cb + 3*16640 + c*32, l0, l1);        // hh lo
            sts128(fh + c*512, h0, h1, l0, l1);
        }
    }
    __syncthreads();                                   // frags ready; canonical dead

    // ---- prefetch xA(0), xB(0) ----
    {
        const __half* gx = g_xh;                       // t=0: rows 0..63
        for (int j = 0; j < 4; ++j) {
            int i = tid + j * NTHR;                    // 0..2047 (group A rows 0-31)
            int row = i >> 6, u = i & 63;
            cp16(sb + (unsigned)(XA_OFF + row*1040 + u*16), gx + row*512 + u*8);
        }
        cp_commit();
        for (int j = 0; j < 4; ++j) {
            int i = tid + j * NTHR;
            int row = i >> 6, u = i & 63;
            cp16(sb + (unsigned)(XB_OFF + row*1040 + u*16), gx + (32 + row)*512 + u*8);
        }
        cp_commit();
    }
    cp_wait0(); __syncthreads();
    const unsigned F0A = sF0[0], F0B = sF0[1];

    // per-warp constant addresses
    const unsigned aXA = sb + (unsigned)(XA_OFF + (mt*16 + (lane & 15))*1040
                                         + (lane >> 4)*16 + kq*256);
    const unsigned aXB = aXA + (XB_OFF - XA_OFF);
    const unsigned aHA = aXA + (HA_OFF - XA_OFF);
    const unsigned aHB = aXA + (HB_OFF - XA_OFF);
    const unsigned fIh = sb + FIH_OFF + (unsigned)(((nt*4 + kq)*8)*512 + lane*16);
    const unsigned fHh = sb + FHH_OFF + (unsigned)(((nt*4 + kq)*8)*512 + lane*16);

    const int brow = mt*16 + (lane >> 2);              // group-local batch row of c0/c1
    const int pcol = nt*8 + (lane & 3)*2;
    float* ppA = partA + (kq*32 + brow)*18 + pcol;
    float* ppB = partB + (kq*32 + brow)*18 + pcol;

    const int ub = (tid & 127) >> 2, uhcl = tid & 3;   // update identity within group

    float cst = 0.0f;                                  // cstA for tid<128, cstB for 128..255

    for (int t = 0; t < SEQL; ++t) {
        // ================= A phase =================
        if (t > 0) {                                   // stage hA(t-1) (poll done last iter)
            const __half* hs = g_hA[(t - 1) & 1];
            for (int j = 0; j < 4; ++j) {
                int i = tid + j * NTHR;
                int row = i >> 6, u = i & 63;
                cp16(sb + (unsigned)(HA_OFF + row*1040 + u*16), hs + row*512 + u*8);
            }
            cp_commit();
        }

        float c0 = 0.f, c1 = 0.f, c2 = 0.f, c3 = 0.f;
        // x-MMA A (XA resident: drained at previous B-phase wait / setup)
#pragma unroll
        for (int c = 0; c < 8; ++c) {
            unsigned a0,a1,a2,a3, b0,b1,b2,b3;
            ldsm4(aXA + c*32, a0,a1,a2,a3);
            lds128(fIh + c*512, b0,b1,b2,b3);
            mmaf16(c0,c1,c2,c3, a0,a1,a2,a3, b0,b1);
            mmaf16(c0,c1,c2,c3, a0,a1,a2,a3, b2,b3);
        }
        cp_wait0(); __syncthreads();                   // hA landed (+ leftover x)
        if (t > 0) {
#pragma unroll
            for (int c = 0; c < 8; ++c) {
                unsigned a0,a1,a2,a3, b0,b1,b2,b3;
                ldsm4(aHA + c*32, a0,a1,a2,a3);
                lds128(fHh + c*512, b0,b1,b2,b3);
                mmaf16(c0,c1,c2,c3, a0,a1,a2,a3, b0,b1);
                mmaf16(c0,c1,c2,c3, a0,a1,a2,a3, b2,b3);
            }
        }
        ppA[0] = c0; ppA[1] = c1; ppA[8*18] = c2; ppA[8*18 + 1] = c3;
        __syncthreads();

        if (tid < 128) {                               // update A
            float sv[4];
#pragma unroll
            for (int g = 0; g < 4; ++g) {
                int r = g*4 + uhcl;
                float s = bias[r];
#pragma unroll
                for (int q = 0; q < 4; ++q) s += partA[(q*32 + ub)*18 + r];
                sv[g] = s;
            }
            float ig = sigm(sv[0]), fg = sigm(sv[1]);
            float gv = ftanh(sv[2]), og = sigm(sv[3]);
            float cn = fmaf(fg, cst, ig * gv);
            cst = cn;
            float hn = og * ftanh(cn);
            g_hA[t & 1][ub*512 + hc0 + uhcl] = __float2half(hn);
            out[(size_t)t * BATCH * HID + (size_t)ub * HID + hc0 + uhcl] = hn;
            if (t == SEQL - 1)
                out[(size_t)SEQL * BATCH * HID + (size_t)ub * HID + hc0 + uhcl] = hn;
        } else if (wid >= 8) {                         // poll B(t), warps 8-15: 16 flags each
            unsigned tgt = F0B + (unsigned)t;
            unsigned* fp = &g_flagsB[((wid - 8) << 4) + (lane & 15)];
            for (;;) {
                unsigned f = ld_acq(fp);
                if (__all_sync(0xffffffffu, (int)(f - tgt) >= 0)) break;
            }
        }
        __syncthreads();
        if (tid == 0) st_rel(&g_flagsA[cta], F0A + (unsigned)(t + 1));

        if (t + 1 < SEQL) {                            // prefetch xA(t+1)
            const __half* gx = g_xh + (size_t)(t + 1) * BATCH * 512;
            for (int j = 0; j < 4; ++j) {
                int i = tid + j * NTHR;
                int row = i >> 6, u = i & 63;
                cp16(sb + (unsigned)(XA_OFF + row*1040 + u*16), gx + row*512 + u*8);
            }
            cp_commit();
        }

        // ================= B phase =================
        if (t > 0) {                                   // stage hB(t-1) (polled above)
            const __half* hs = g_hB[(t - 1) & 1];
            for (int j = 0; j < 4; ++j) {
                int i = tid + j * NTHR;
                int row = i >> 6, u = i & 63;
                cp16(sb + (unsigned)(HB_OFF + row*1040 + u*16), hs + row*512 + u*8);
            }
            cp_commit();
        }

        c0 = 0.f; c1 = 0.f; c2 = 0.f; c3 = 0.f;
#pragma unroll
        for (int c = 0; c < 8; ++c) {
            unsigned a0,a1,a2,a3, b0,b1,b2,b3;
            ldsm4(aXB + c*32, a0,a1,a2,a3);
            lds128(fIh + c*512, b0,b1,b2,b3);
            mmaf16(c0,c1,c2,c3, a0,a1,a2,a3, b0,b1);
            mmaf16(c0,c1,c2,c3, a0,a1,a2,a3, b2,b3);
        }
        cp_wait0(); __syncthreads();                   // hB + xA(t+1) landed
        if (t > 0) {
#pragma unroll
            for (int c = 0; c < 8; ++c) {
                unsigned a0,a1,a2,a3, b0,b1,b2,b3;
                ldsm4(aHB + c*32, a0,a1,a2,a3);
                lds128(fHh + c*512, b0,b1,b2,b3);
                mmaf16(c0,c1,c2,c3, a0,a1,a2,a3, b0,b1);
                mmaf16(c0,c1,c2,c3, a0,a1,a2,a3, b2,b3);
            }
        }
        ppB[0] = c0; ppB[1] = c1; ppB[8*18] = c2; ppB[8*18 + 1] = c3;
        __syncthreads();

        if (tid >= 128 && tid < 256) {                 // update B (global rows 32+)
            float sv[4];
#pragma unroll
            for (int g = 0; g < 4; ++g) {
                int r = g*4 + uhcl;
                float s = bias[r];
#pragma unroll
                for (int q = 0; q < 4; ++q) s += partB[(q*32 + ub)*18 + r];
                sv[g] = s;
            }
            float ig = sigm(sv[0]), fg = sigm(sv[1]);
            float gv = ftanh(sv[2]), og = sigm(sv[3]);
            float cn = fmaf(fg, cst, ig * gv);
            cst = cn;
            float hn = og * ftanh(cn);
            g_hB[t & 1][ub*512 + hc0 + uhcl] = __float2half(hn);
            int gb = 32 + ub;
            out[(size_t)t * BATCH * HID + (size_t)gb * HID + hc0 + uhcl] = hn;
            if (t == SEQL - 1)
                out[(size_t)SEQL * BATCH * HID + (size_t)gb * HID + hc0 + uhcl] = hn;
        } else if (wid >= 8) {                         // poll A(t+1)
            if (t + 1 < SEQL) {
                unsigned tgt = F0A + (unsigned)(t + 1);
                unsigned* fp = &g_flagsA[((wid - 8) << 4) + (lane & 15)];
                for (;;) {
                    unsigned f = ld_acq(fp);
                    if (__all_sync(0xffffffffu, (int)(f - tgt) >= 0)) break;
                }
            }
        }
        __syncthreads();
        if (tid == 0) st_rel(&g_flagsB[cta], F0B + (unsigned)(t + 1));

        if (t + 1 < SEQL) {                            // prefetch xB(t+1)
            const __half* gx = g_xh + (size_t)(t + 1) * BATCH * 512;
            for (int j = 0; j < 4; ++j) {
                int i = tid + j * NTHR;
                int row = i >> 6, u = i & 63;
                cp16(sb + (unsigned)(XB_OFF + row*1040 + u*16), gx + (32 + row)*512 + u*8);
            }
            cp_commit();
        }
    }

    // c_n
    if (tid < 128)
        out[(size_t)SEQL * BATCH * HID + (size_t)BATCH * HID
            + (size_t)ub * HID + hc0 + uhcl] = cst;
    else if (tid < 256)
        out[(size_t)SEQL * BATCH * HID + (size_t)BATCH * HID
            + (size_t)(32 + ub) * HID + hc0 + uhcl] = cst;
}

extern "C" void kernel_launch(void* const* d_in, const int* in_sizes, int n_in,
                              void* d_out, int out_size)
{
    const float* input = (const float*)d_in[0];
    const float* Wih   = (const float*)d_in[1];
    const float* Whh   = (const float*)d_in[2];
    const float* bih   = (const float*)d_in[3];
    const float* bhh   = (const float*)d_in[4];
    float* out = (float*)d_out;

    static int configured = 0;
    if (!configured) {
        cudaFuncSetAttribute(lstm_persistent,
                             cudaFuncAttributeMaxDynamicSharedMemorySize, SMEM_TOTAL);
        configured = 1;
    }

    xconv<<<SEQL, 256>>>(input);
    lstm_persistent<<<NCTA, NTHR, SMEM_TOTAL>>>(Wih, Whh, bih, bhh, out);
}